// round 2
// baseline (speedup 1.0000x reference)
#include <cuda_runtime.h>
#include <math.h>

#define HH 80
#define WW 80
#define NPIX 6400
#define CC 6
#define LL 6
#define CL 36          // LL*CC
#define SPLITK 20
#define KCHUNK 320     // NPIX/SPLITK, divisible by 32
#define NB_ELBO 25

// ---- scratch (device globals: allocation-free rule) ----
__device__ float g_Kb[NPIX * NPIX];       // 164 MB bilateral kernel
__device__ float g_normb[NPIX];
__device__ float g_G[HH * HH];            // 1D spatial gaussian (theta_gamma)
__device__ float g_Snorm[HH];
__device__ float4 g_z4[NPIX];             // scaled (y,x,f0,f1)
__device__ float  g_z1[NPIX];             // scaled f2
__device__ float g_unary[CC * NPIX];
__device__ float g_Q[CL * NPIX];
__device__ float g_SM[CL * NPIX];
__device__ float g_tmp[CL * NPIX];
__device__ float g_Fs[CL * NPIX];
__device__ float g_Fb[CL * NPIX];
__device__ float g_part[SPLITK * CL * NPIX];   // split-K partials (18.4 MB)
__device__ float g_As[CC * CC];           // compat @ Wsp
__device__ float g_Ab[CC * CC];           // compat @ Wbl
__device__ float g_epart[LL * NB_ELBO];

// ---- prep: scaled coords, transposed unary, Q init ----
__global__ void k_prep(const float* __restrict__ unary, const float* __restrict__ feat) {
    int p = blockIdx.x * blockDim.x + threadIdx.x;
    if (p >= NPIX) return;
    int y = p / WW, x = p % WW;
    const float inva = 1.0f / 8.0f;     // 1/theta_alpha
    const float invb = 1.0f / 0.15f;    // 1/theta_beta
    float4 z;
    z.x = (float)y * inva;
    z.y = (float)x * inva;
    z.z = feat[p * 3 + 0] * invb;
    z.w = feat[p * 3 + 1] * invb;
    g_z4[p] = z;
    g_z1[p] = feat[p * 3 + 2] * invb;
    float u[CC];
#pragma unroll
    for (int c = 0; c < CC; c++) {
        u[c] = unary[p * CC + c];
        g_unary[c * NPIX + p] = u[c];
    }
#pragma unroll
    for (int l = 0; l < LL; l++)
#pragma unroll
        for (int c = 0; c < CC; c++)
            g_Q[(l * CC + c) * NPIX + p] = u[c];
}

// ---- prep_small: 1D spatial kernel, its row sums, fused CxC matrices ----
__global__ void k_prep_small(const float* __restrict__ compat,
                             const float* __restrict__ wsp,
                             const float* __restrict__ wbl) {
    int tid = threadIdx.x;
    for (int i = tid; i < HH * HH; i += blockDim.x) {
        int a = i / HH, b = i % HH;
        float d = (float)(a - b);
        g_G[i] = expf(-d * d * (1.0f / 18.0f));   // 2*theta_gamma^2 = 18
    }
    __syncthreads();
    if (tid < HH) {
        float s = 0.f;
        for (int b = 0; b < HH; b++) s += g_G[tid * HH + b];
        g_Snorm[tid] = s;
    }
    if (tid < CC * CC) {
        int i = tid / CC, j = tid % CC;
        float as = 0.f, ab = 0.f;
        for (int k = 0; k < CC; k++) {
            as += compat[i * CC + k] * wsp[k * CC + j];
            ab += compat[i * CC + k] * wbl[k * CC + j];
        }
        g_As[tid] = as;
        g_Ab[tid] = ab;
    }
}

// ---- bilateral kernel matrix + row-sum normalizer ----
__global__ void k_Kb() {
    int i = blockIdx.x;
    float4 zi = g_z4[i];
    float zi1 = g_z1[i];
    int base = i * NPIX;
    float sum = 0.f;
    for (int j = threadIdx.x; j < NPIX; j += blockDim.x) {
        float4 zj = g_z4[j];
        float d0 = zi.x - zj.x, d1 = zi.y - zj.y;
        float d2 = zi.z - zj.z, d3 = zi.w - zj.w;
        float d4 = zi1 - g_z1[j];
        float d = d0 * d0 + d1 * d1 + d2 * d2 + d3 * d3 + d4 * d4;
        float v = __expf(-0.5f * d);
        g_Kb[base + j] = v;
        sum += v;
    }
    __shared__ float red[256];
    red[threadIdx.x] = sum;
    __syncthreads();
    for (int s = 128; s > 0; s >>= 1) {
        if (threadIdx.x < s) red[threadIdx.x] += red[threadIdx.x + s];
        __syncthreads();
    }
    if (threadIdx.x == 0) g_normb[i] = red[0];
}

// ---- per-pixel softmax over C, for all labels ----
__global__ void k_softmax() {
    int t = blockIdx.x * blockDim.x + threadIdx.x;
    if (t >= LL * NPIX) return;
    int l = t / NPIX, p = t % NPIX;
    int base = l * CC * NPIX + p;
    float q[CC], m = -1e30f;
#pragma unroll
    for (int c = 0; c < CC; c++) {
        q[c] = g_Q[base + c * NPIX];
        m = fmaxf(m, q[c]);
    }
    float s = 0.f;
#pragma unroll
    for (int c = 0; c < CC; c++) {
        q[c] = __expf(q[c] - m);
        s += q[c];
    }
    float inv = 1.0f / s;
#pragma unroll
    for (int c = 0; c < CC; c++) g_SM[base + c * NPIX] = q[c] * inv;
}

// ---- separable spatial filtering (exact Ks application) ----
__global__ void k_conv_x() {
    int r = blockIdx.x / HH, y = blockIdx.x % HH;
    int x2 = threadIdx.x;
    __shared__ float row[WW];
    row[x2] = g_SM[r * NPIX + y * WW + x2];
    __syncthreads();
    float acc = 0.f;
#pragma unroll 8
    for (int x = 0; x < WW; x++) acc += row[x] * g_G[x * HH + x2];
    g_tmp[r * NPIX + y * WW + x2] = acc;
}

__global__ void k_conv_y() {
    int r = blockIdx.x / HH, y2 = blockIdx.x % HH;
    int x = threadIdx.x;
    float acc = 0.f;
#pragma unroll 8
    for (int y = 0; y < HH; y++)
        acc += g_tmp[r * NPIX + y * WW + x] * g_G[y * HH + y2];
    g_Fs[r * NPIX + y2 * WW + x] = acc / (g_Snorm[y2] * g_Snorm[x]);
}

// ---- bilateral GEMM: [36 x N] @ Kb[N x N], split-K partials ----
__global__ void k_gemm() {
    int col = blockIdx.x * 256 + threadIdx.x;
    int k0base = blockIdx.y * KCHUNK;
    float acc[CL];
#pragma unroll
    for (int r = 0; r < CL; r++) acc[r] = 0.f;
    __shared__ float sA[32 * CL];
    for (int k0 = k0base; k0 < k0base + KCHUNK; k0 += 32) {
        for (int idx = threadIdx.x; idx < 32 * CL; idx += 256) {
            int r = idx >> 5, kk = idx & 31;
            sA[kk * CL + r] = g_SM[r * NPIX + k0 + kk];
        }
        __syncthreads();
#pragma unroll 4
        for (int kk = 0; kk < 32; kk++) {
            float b = g_Kb[(k0 + kk) * NPIX + col];
            const float* a = &sA[kk * CL];
#pragma unroll
            for (int r = 0; r < CL; r++) acc[r] += a[r] * b;
        }
        __syncthreads();
    }
#pragma unroll
    for (int r = 0; r < CL; r++)
        g_part[(blockIdx.y * CL + r) * NPIX + col] = acc[r];
}

// ---- split-K reduce + normalizer divide ----
__global__ void k_reduce() {
    int t = blockIdx.x * 256 + threadIdx.x;
    if (t >= CL * NPIX) return;
    int p = t % NPIX;
    float s = 0.f;
#pragma unroll
    for (int sp = 0; sp < SPLITK; sp++) s += g_part[sp * CL * NPIX + t];
    g_Fb[t] = s / g_normb[p];
}

// ---- q update: q = unary + lg_col - (As@Fs + Ab@Fb) ----
__global__ void k_update(const float* __restrict__ lg) {
    int t = blockIdx.x * 256 + threadIdx.x;
    if (t >= LL * NPIX) return;
    int l = t / NPIX, p = t % NPIX;
    int base = l * CC * NPIX + p;
    float fs[CC], fb[CC];
#pragma unroll
    for (int c = 0; c < CC; c++) {
        fs[c] = g_Fs[base + c * NPIX];
        fb[c] = g_Fb[base + c * NPIX];
    }
#pragma unroll
    for (int c = 0; c < CC; c++) {
        float pw = 0.f;
#pragma unroll
        for (int k = 0; k < CC; k++)
            pw += g_As[c * CC + k] * fs[k] + g_Ab[c * CC + k] * fb[k];
        g_Q[base + c * NPIX] = g_unary[c * NPIX + p] + lg[c * CC + l] - pw;
    }
}

// ---- ELBO: sum_p sum_c sm*(unary + lg - msg) - sm*log(sm+1e-10) ----
__global__ void k_elbo(const float* __restrict__ wsp,
                       const float* __restrict__ wbl,
                       const float* __restrict__ lg) {
    int l = blockIdx.y;
    int base_l = l * CC * NPIX;
    float acc = 0.f;
    for (int p = blockIdx.x * 256 + threadIdx.x; p < NPIX; p += NB_ELBO * 256) {
        float sm[CC], fs[CC], fb[CC];
#pragma unroll
        for (int c = 0; c < CC; c++) {
            sm[c] = g_SM[base_l + c * NPIX + p];
            fs[c] = g_Fs[base_l + c * NPIX + p];
            fb[c] = g_Fb[base_l + c * NPIX + p];
        }
#pragma unroll
        for (int c = 0; c < CC; c++) {
            float msg = 0.f;
#pragma unroll
            for (int k = 0; k < CC; k++)
                msg += wsp[c * CC + k] * fs[k] + wbl[c * CC + k] * fb[k];
            acc += sm[c] * (g_unary[c * NPIX + p] + lg[c * CC + l] - msg)
                 - sm[c] * logf(sm[c] + 1e-10f);
        }
    }
    __shared__ float red[256];
    red[threadIdx.x] = acc;
    __syncthreads();
    for (int s = 128; s > 0; s >>= 1) {
        if (threadIdx.x < s) red[threadIdx.x] += red[threadIdx.x + s];
        __syncthreads();
    }
    if (threadIdx.x == 0) g_epart[l * NB_ELBO + blockIdx.x] = red[0];
}

__global__ void k_final(float* __restrict__ out) {
    int l = threadIdx.x;
    if (l < LL) {
        float s = 0.f;
        for (int b = 0; b < NB_ELBO; b++) s += g_epart[l * NB_ELBO + b];
        out[l] = s;
    }
}

extern "C" void kernel_launch(void* const* d_in, const int* in_sizes, int n_in,
                              void* d_out, int out_size) {
    const float* unary  = (const float*)d_in[0];   // (1,80,80,6)
    const float* feat   = (const float*)d_in[1];   // (80,80,3)
    const float* compat = (const float*)d_in[2];   // (6,6)
    const float* lg     = (const float*)d_in[3];   // (6,6)
    const float* wsp    = (const float*)d_in[4];   // (6,6)
    const float* wbl    = (const float*)d_in[5];   // (6,6)
    float* out = (float*)d_out;

    k_prep<<<25, 256>>>(unary, feat);
    k_prep_small<<<1, 128>>>(compat, wsp, wbl);
    k_Kb<<<NPIX, 256>>>();

    for (int it = 0; it < 5; it++) {
        k_softmax<<<150, 256>>>();
        k_conv_x<<<CL * HH, WW>>>();
        k_conv_y<<<CL * HH, WW>>>();
        k_gemm<<<dim3(25, SPLITK), 256>>>();
        k_reduce<<<900, 256>>>();
        if (it < 4) k_update<<<150, 256>>>(lg);
    }
    k_elbo<<<dim3(NB_ELBO, LL), 256>>>(wsp, wbl, lg);
    k_final<<<1, 32>>>(out);
}